// round 3
// baseline (speedup 1.0000x reference)
#include <cuda_runtime.h>
#include <math.h>

// ---------------- problem constants (fixed by the dataset) ----------------
#define BB   16
#define LL   4096
#define NR   (BB*LL)      // 65536 rows
#define DD   512          // input feature dim
#define CC   128          // projection dim
#define HH   4
#define DK   32
#define MM   512          // output dim
#define NCHUNK 32         // L-chunks for score reduction (4096/128)
#define SCALE_F 0.17677669529663687f   // 1/sqrt(32)

// ---------------- device scratch (static, allocation-free) ----------------
__device__ float g_Qm[(size_t)NR * CC];          // 33.5 MB
__device__ float g_Km[(size_t)NR * CC];
__device__ float g_Vm[(size_t)NR * CC];
__device__ float g_part[(size_t)NCHUNK * BB * HH * DK * DK];   // 8 MB partial scores
__device__ float g_attn[BB * HH * DK * DK];
__device__ float g_WoEff[(size_t)BB * CC * MM];  // 4 MB

// =====================================================================
// K1: fused QKV projection.  A(N x 512) @ W(512 x BN) + bias.
//   KV=false: A=Q_in, W=Wq  -> g_Qm          (BN=128, TN=8)
//   KV=true : A=KV_in, W=[Wk|Wv] -> g_Km,g_Vm (BN=256, TN=16)
// BM=64, BK=32, 256 threads, thread tile 4 x TN.
// =====================================================================
template<bool KV>
__global__ void __launch_bounds__(256) k_qkv(
    const float* __restrict__ A,
    const float* __restrict__ W0, const float* __restrict__ b0v,
    const float* __restrict__ W1, const float* __restrict__ b1v)
{
    constexpr int BN = KV ? 256 : 128;
    constexpr int TN = KV ? 16 : 8;
    __shared__ float As[32][64];
    __shared__ float Ws[32][BN];

    const int t  = threadIdx.x;
    const int tx = t & 15;        // 16 col-thread groups
    const int ty = t >> 4;        // 16 row-thread groups (4 rows each)
    const int row0 = blockIdx.x * 64;

    float acc[4][TN];
#pragma unroll
    for (int r = 0; r < 4; r++)
#pragma unroll
        for (int c = 0; c < TN; c++) acc[r][c] = 0.f;

    for (int kk = 0; kk < DD; kk += 32) {
        // load A tile (64 rows x 32 k), store transposed As[k][row]
#pragma unroll
        for (int i = 0; i < 2; i++) {
            int f = t * 2 + i;               // 0..511 float4s
            int r = f >> 3, kq = (f & 7) * 4;
            float4 v = *(const float4*)(A + (size_t)(row0 + r) * DD + kk + kq);
            As[kq+0][r] = v.x; As[kq+1][r] = v.y; As[kq+2][r] = v.z; As[kq+3][r] = v.w;
        }
        // load W tile (32 x BN)
#pragma unroll
        for (int i = 0; i < BN/32; i++) {
            int f = i * 256 + t;             // 0..BN*8-1 float4s
            int k = f / (BN/4);
            int n = (f % (BN/4)) * 4;
            const float* src;
            if (KV) src = (n < 128) ? (W0 + (size_t)(kk + k) * 128 + n)
                                    : (W1 + (size_t)(kk + k) * 128 + (n - 128));
            else    src = W0 + (size_t)(kk + k) * 128 + n;
            *(float4*)&Ws[k][n] = *(const float4*)src;
        }
        __syncthreads();
#pragma unroll 8
        for (int k = 0; k < 32; k++) {
            float4 av = *(const float4*)&As[k][ty*4];
            float ar[4] = {av.x, av.y, av.z, av.w};
            float br[TN];
#pragma unroll
            for (int j = 0; j < TN/4; j++) {
                float4 bv = *(const float4*)&Ws[k][tx*TN + j*4];
                br[j*4+0]=bv.x; br[j*4+1]=bv.y; br[j*4+2]=bv.z; br[j*4+3]=bv.w;
            }
#pragma unroll
            for (int r = 0; r < 4; r++)
#pragma unroll
                for (int c = 0; c < TN; c++)
                    acc[r][c] = fmaf(ar[r], br[c], acc[r][c]);
        }
        __syncthreads();
    }
    // epilogue: bias + store
#pragma unroll
    for (int j = 0; j < TN/4; j++) {
        int col = tx*TN + j*4;
        float4 bias;
        if (KV) bias = (col < 128) ? *(const float4*)(b0v + col)
                                   : *(const float4*)(b1v + col - 128);
        else    bias = *(const float4*)(b0v + col);
#pragma unroll
        for (int r = 0; r < 4; r++) {
            int row = row0 + ty*4 + r;
            float4 o;
            o.x = acc[r][j*4+0] + bias.x;
            o.y = acc[r][j*4+1] + bias.y;
            o.z = acc[r][j*4+2] + bias.z;
            o.w = acc[r][j*4+3] + bias.w;
            if (!KV)            *(float4*)(g_Qm + (size_t)row*CC + col) = o;
            else if (col < 128) *(float4*)(g_Km + (size_t)row*CC + col) = o;
            else                *(float4*)(g_Vm + (size_t)row*CC + (col-128)) = o;
        }
    }
}

// =====================================================================
// K2: partial scores. grid (chunk=32, bh=64). block 256.
// scores[b,h,d,e] partial over 128 seq positions -> g_part[chunk][...]
// =====================================================================
__global__ void __launch_bounds__(256) k_scores()
{
    __shared__ float Qs[128][32];
    __shared__ float Ks[128][32];
    const int t = threadIdx.x;
    const int chunk = blockIdx.x;
    const int bh = blockIdx.y;
    const int b = bh >> 2, h = bh & 3;
    const int rowbase = b * LL + chunk * 128;

#pragma unroll
    for (int i = 0; i < 4; i++) {
        int f = i * 256 + t;                 // 0..1023 float4s
        int r = f >> 3, j = (f & 7) * 4;
        *(float4*)&Qs[r][j] = *(const float4*)(g_Qm + (size_t)(rowbase + r)*CC + h*DK + j);
        *(float4*)&Ks[r][j] = *(const float4*)(g_Km + (size_t)(rowbase + r)*CC + h*DK + j);
    }
    __syncthreads();

    const int tile = t & 63, ly = t >> 6;
    const int d0 = (tile >> 3) * 4, e0 = (tile & 7) * 4;
    float acc[4][4];
#pragma unroll
    for (int r = 0; r < 4; r++)
#pragma unroll
        for (int c = 0; c < 4; c++) acc[r][c] = 0.f;

    for (int l = ly; l < 128; l += 4) {
        float4 q = *(const float4*)&Qs[l][d0];
        float4 k = *(const float4*)&Ks[l][e0];
        float qa[4] = {q.x,q.y,q.z,q.w};
        float ka[4] = {k.x,k.y,k.z,k.w};
#pragma unroll
        for (int r = 0; r < 4; r++)
#pragma unroll
            for (int c = 0; c < 4; c++)
                acc[r][c] = fmaf(qa[r], ka[c], acc[r][c]);
    }
    __syncthreads();           // done reading Qs, safe to alias
    float* red = &Qs[0][0];    // 4096 floats = 256 threads * 16
#pragma unroll
    for (int r = 0; r < 4; r++)
#pragma unroll
        for (int c = 0; c < 4; c++) red[t*16 + r*4 + c] = acc[r][c];
    __syncthreads();
    if (t < 64) {
        const int dd0 = (t >> 3) * 4, ee0 = (t & 7) * 4;
#pragma unroll
        for (int i = 0; i < 16; i++) {
            float s = red[t*16+i] + red[(t+64)*16+i] + red[(t+128)*16+i] + red[(t+192)*16+i];
            int r = i >> 2, c = i & 3;
            g_part[(size_t)chunk * 65536 + bh*1024 + (dd0+r)*32 + (ee0+c)] = s;
        }
    }
}

// =====================================================================
// K3: reduce partials + softmax over e. grid 64, block 1024 (warp = row d).
// =====================================================================
__global__ void __launch_bounds__(1024) k_softmax(float* __restrict__ attn_out)
{
    const int bh = blockIdx.x;
    const int t = threadIdx.x;
    float s = 0.f;
#pragma unroll
    for (int c = 0; c < NCHUNK; c++) s += g_part[(size_t)c*65536 + bh*1024 + t];
    s *= SCALE_F;
    float m = s;
#pragma unroll
    for (int o = 16; o; o >>= 1) m = fmaxf(m, __shfl_xor_sync(0xffffffffu, m, o));
    float ex = expf(s - m);
    float sum = ex;
#pragma unroll
    for (int o = 16; o; o >>= 1) sum += __shfl_xor_sync(0xffffffffu, sum, o);
    float a = ex / sum;
    g_attn[bh*1024 + t] = a;
    if (attn_out) attn_out[bh*1024 + t] = a;
}

// =====================================================================
// K4: Wo_eff[b][h*32+e][m] = sum_d attn[b,h,d,e] * Wo[h*32+d][m]
// grid (m_tiles=16, b=16), block 256.
// =====================================================================
__global__ void __launch_bounds__(256) k_woeff(const float* __restrict__ Wo)
{
    __shared__ float at[4096];        // attn for this batch, flat h*1024+d*32+e
    __shared__ float wo_s[128][32];
    const int m0 = blockIdx.x * 32;
    const int b  = blockIdx.y;
    const int t  = threadIdx.x;
#pragma unroll
    for (int i = 0; i < 4; i++) {
        int f = i*256 + t;            // 0..1023 float4s
        *(float4*)&at[f*4] = *(const float4*)(g_attn + (size_t)b*4096 + f*4);
    }
#pragma unroll
    for (int i = 0; i < 4; i++) {
        int f = i*256 + t;
        int r = f >> 3, c = (f & 7) * 4;
        *(float4*)&wo_s[r][c] = *(const float4*)(Wo + (size_t)r*MM + m0 + c);
    }
    __syncthreads();
    const int tx = t & 31, ty = t >> 5;   // ty 0..7
#pragma unroll
    for (int i = 0; i < 16; i++) {
        int he = ty + 8*i;                // 0..127
        int h = he >> 5, e = he & 31;
        float s = 0.f;
#pragma unroll
        for (int d = 0; d < 32; d++)
            s = fmaf(at[h*1024 + d*32 + e], wo_s[h*32+d][tx], s);
        g_WoEff[((size_t)b*CC + he)*MM + m0 + tx] = s;
    }
}

// =====================================================================
// K5: fused final GEMM + LayerNorm.
// x[row,:] = Qm[row] @ Wqo + Vm[row] @ WoEff[b] + (bqo+bo); y = LN(x)*gamma+beta
// BM=32 rows, BN=512 (full M), BK=16. 256 threads, thread tile 4x16.
// warp = (ty fixed, tx 0..31) owns rows ty*4..ty*4+3 -> shuffle LN.
// =====================================================================
__global__ void __launch_bounds__(256) k_final(
    const float* __restrict__ Wqo, const float* __restrict__ bqo,
    const float* __restrict__ bo,  const float* __restrict__ gamma,
    const float* __restrict__ beta, float* __restrict__ Y)
{
    __shared__ float As[16][32];
    __shared__ float Ws[16][512];
    const int t = threadIdx.x;
    const int tx = t & 31, ty = t >> 5;    // ty 0..7
    const int row0 = blockIdx.x * 32;
    const int b = row0 >> 12;              // 4096 rows per batch

    float acc[4][16];
#pragma unroll
    for (int r = 0; r < 4; r++)
#pragma unroll
        for (int c = 0; c < 16; c++) acc[r][c] = 0.f;

    for (int kk = 0; kk < 256; kk += 16) {
        if (t < 128) {                      // A tile: 32 rows x 16 k
            int r = t >> 2, j = (t & 3) * 4;
            int kg = kk + j;
            const float* src = (kg < 128) ? (g_Qm + (size_t)(row0+r)*CC + kg)
                                          : (g_Vm + (size_t)(row0+r)*CC + kg - 128);
            float4 v = *(const float4*)src;
            As[j+0][r]=v.x; As[j+1][r]=v.y; As[j+2][r]=v.z; As[j+3][r]=v.w;
        }
#pragma unroll
        for (int i = 0; i < 8; i++) {       // W tile: 16 x 512
            int f = i*256 + t;              // 0..2047 float4s
            int k = f >> 7, n = (f & 127) * 4;
            int kg = kk + k;
            const float* src = (kg < 128) ? (Wqo + (size_t)kg*MM + n)
                                          : (g_WoEff + ((size_t)b*CC + kg - 128)*MM + n);
            *(float4*)&Ws[k][n] = *(const float4*)src;
        }
        __syncthreads();
#pragma unroll 8
        for (int k = 0; k < 16; k++) {
            float4 av = *(const float4*)&As[k][ty*4];
            float ar[4] = {av.x, av.y, av.z, av.w};
            float br[16];
#pragma unroll
            for (int j = 0; j < 4; j++) {
                float4 bv = *(const float4*)&Ws[k][tx*16 + j*4];
                br[j*4+0]=bv.x; br[j*4+1]=bv.y; br[j*4+2]=bv.z; br[j*4+3]=bv.w;
            }
#pragma unroll
            for (int r = 0; r < 4; r++)
#pragma unroll
                for (int c = 0; c < 16; c++)
                    acc[r][c] = fmaf(ar[r], br[c], acc[r][c]);
        }
        __syncthreads();
    }

    // epilogue: bias + LayerNorm (warp owns full 512-wide rows)
    float bias[16], gm[16], bt[16];
#pragma unroll
    for (int j = 0; j < 4; j++) {
        int col = tx*16 + j*4;
        float4 b1 = *(const float4*)(bqo + col);
        float4 b2 = *(const float4*)(bo + col);
        float4 g4 = *(const float4*)(gamma + col);
        float4 e4 = *(const float4*)(beta + col);
        bias[j*4+0]=b1.x+b2.x; bias[j*4+1]=b1.y+b2.y; bias[j*4+2]=b1.z+b2.z; bias[j*4+3]=b1.w+b2.w;
        gm[j*4+0]=g4.x; gm[j*4+1]=g4.y; gm[j*4+2]=g4.z; gm[j*4+3]=g4.w;
        bt[j*4+0]=e4.x; bt[j*4+1]=e4.y; bt[j*4+2]=e4.z; bt[j*4+3]=e4.w;
    }
#pragma unroll
    for (int r = 0; r < 4; r++) {
        int row = row0 + ty*4 + r;
        float x[16];
        float sum = 0.f, sq = 0.f;
#pragma unroll
        for (int c = 0; c < 16; c++) {
            x[c] = acc[r][c] + bias[c];
            sum += x[c];
            sq  = fmaf(x[c], x[c], sq);
        }
#pragma unroll
        for (int o = 16; o; o >>= 1) {
            sum += __shfl_xor_sync(0xffffffffu, sum, o);
            sq  += __shfl_xor_sync(0xffffffffu, sq,  o);
        }
        float mu  = sum * (1.f/512.f);
        float var = sq * (1.f/512.f) - mu*mu;
        float inv = rsqrtf(var + 1e-5f);
#pragma unroll
        for (int j = 0; j < 4; j++) {
            float4 o4;
            o4.x = (x[j*4+0]-mu)*inv*gm[j*4+0] + bt[j*4+0];
            o4.y = (x[j*4+1]-mu)*inv*gm[j*4+1] + bt[j*4+1];
            o4.z = (x[j*4+2]-mu)*inv*gm[j*4+2] + bt[j*4+2];
            o4.w = (x[j*4+3]-mu)*inv*gm[j*4+3] + bt[j*4+3];
            *(float4*)(Y + (size_t)row*MM + tx*16 + j*4) = o4;
        }
    }
}

// =====================================================================
extern "C" void kernel_launch(void* const* d_in, const int* in_sizes, int n_in,
                              void* d_out, int out_size)
{
    const float* Q_in  = (const float*)d_in[0];
    const float* KV_in = (const float*)d_in[1];
    const float* Wq    = (const float*)d_in[2];
    const float* bq    = (const float*)d_in[3];
    const float* Wk    = (const float*)d_in[4];
    const float* bk    = (const float*)d_in[5];
    const float* Wv    = (const float*)d_in[6];
    const float* bv    = (const float*)d_in[7];
    const float* Wo    = (const float*)d_in[8];
    const float* bo    = (const float*)d_in[9];
    const float* Wqo   = (const float*)d_in[10];
    const float* bqo   = (const float*)d_in[11];
    const float* gamma = (const float*)d_in[12];
    const float* beta  = (const float*)d_in[13];
    float* out = (float*)d_out;

    const long long y_elems = (long long)NR * MM;             // 33,554,432
    const long long a_elems = (long long)BB * HH * DK * DK;   // 65,536
    float* attn_out = ((long long)out_size >= y_elems + a_elems) ? (out + y_elems) : nullptr;

    k_qkv<false><<<NR/64, 256>>>(Q_in,  Wq, bq, nullptr, nullptr);
    k_qkv<true ><<<NR/64, 256>>>(KV_in, Wk, bk, Wv, bv);
    k_scores<<<dim3(NCHUNK, BB*HH), 256>>>();
    k_softmax<<<BB*HH, 1024>>>(attn_out);
    k_woeff<<<dim3(MM/32, BB), 256>>>(Wo);
    k_final<<<NR/32, 256>>>(Wqo, bqo, bo, gamma, beta, out);
}

// round 5
// speedup vs baseline: 3.1976x; 3.1976x over previous
#include <cuda_runtime.h>
#include <cuda_bf16.h>
#include <math.h>

// ---------------- problem constants ----------------
#define BB   16
#define LL   4096
#define NR   (BB*LL)      // 65536 rows
#define DD   512
#define CC   128
#define HH   4
#define DK   32
#define MM   512
#define NCHUNK 32
#define SCALE_F 0.17677669529663687f

// ---------------- device scratch ----------------
// Qm/Km/Vm stored packed: low16 = bf16(hi), high16 = bf16(residual)
__device__ unsigned g_Qm[(size_t)NR * CC];
__device__ unsigned g_Km[(size_t)NR * CC];
__device__ unsigned g_Vm[(size_t)NR * CC];
__device__ float    g_part[(size_t)NCHUNK * BB * HH * DK * DK];
__device__ float    g_attn[BB * HH * DK * DK];
__device__ float    g_X[(size_t)NR * MM];          // pre-LN activations
// transposed + split weights: [n][k] layout, k contiguous
__device__ unsigned short g_WqT_hi [128 * 512], g_WqT_lo [128 * 512];
__device__ unsigned short g_WkvT_hi[256 * 512], g_WkvT_lo[256 * 512];
__device__ unsigned short g_WqoT_hi[512 * 128], g_WqoT_lo[512 * 128];
__device__ unsigned short g_WoT_hi [16 * 512 * 128], g_WoT_lo[16 * 512 * 128];

// ---------------- helpers ----------------
__device__ __forceinline__ void split2(float x, unsigned short& h, unsigned short& l)
{
    __nv_bfloat16 hb = __float2bfloat16(x);
    float r = x - __bfloat162float(hb);
    __nv_bfloat16 lb = __float2bfloat16(r);
    h = __bfloat16_as_ushort(hb);
    l = __bfloat16_as_ushort(lb);
}
__device__ __forceinline__ unsigned packf(float x)
{
    unsigned short h, l; split2(x, h, l);
    return (unsigned)h | ((unsigned)l << 16);
}
__device__ __forceinline__ float unpackf(unsigned u)
{
    float h = __bfloat162float(__ushort_as_bfloat16((unsigned short)(u & 0xffffu)));
    float l = __bfloat162float(__ushort_as_bfloat16((unsigned short)(u >> 16)));
    return h + l;
}
__device__ __forceinline__ void mma16816(float* c, const unsigned* a, const unsigned* b)
{
    asm volatile(
        "mma.sync.aligned.m16n8k16.row.col.f32.bf16.bf16.f32 "
        "{%0,%1,%2,%3}, {%4,%5,%6,%7}, {%8,%9}, {%0,%1,%2,%3};"
        : "+f"(c[0]), "+f"(c[1]), "+f"(c[2]), "+f"(c[3])
        : "r"(a[0]), "r"(a[1]), "r"(a[2]), "r"(a[3]), "r"(b[0]), "r"(b[1]));
}

// =====================================================================
// k_prep: build transposed, bf16-split weight copies.
// =====================================================================
__global__ void __launch_bounds__(256) k_prep(
    const float* __restrict__ Wq, const float* __restrict__ Wk,
    const float* __restrict__ Wv, const float* __restrict__ Wqo)
{
    int e = blockIdx.x * 256 + threadIdx.x;      // 0..262143
    unsigned short h, l;
    if (e < 65536) {                              // WqT [128][512]
        int n = e >> 9, k = e & 511;
        split2(Wq[(size_t)k * 128 + n], h, l);
        g_WqT_hi[(size_t)n * 512 + k] = h; g_WqT_lo[(size_t)n * 512 + k] = l;
    } else if (e < 196608) {                      // WkvT [256][512]
        int e2 = e - 65536;
        int n = e2 >> 9, k = e2 & 511;
        float v = (n < 128) ? Wk[(size_t)k * 128 + n] : Wv[(size_t)k * 128 + (n - 128)];
        split2(v, h, l);
        g_WkvT_hi[(size_t)n * 512 + k] = h; g_WkvT_lo[(size_t)n * 512 + k] = l;
    } else {                                      // WqoT [512][128]
        int e2 = e - 196608;
        int n = e2 >> 7, k = e2 & 127;
        split2(Wqo[(size_t)k * 512 + n], h, l);
        g_WqoT_hi[(size_t)n * 128 + k] = h; g_WqoT_lo[(size_t)n * 128 + k] = l;
    }
}

// =====================================================================
// K1: QKV projection via bf16-split MMA.
// C(128x128 per CTA) = A(row tile x 512 fp32) @ WT^T, +bias, packed store.
// 256 threads = 8 warps in 4(M) x 2(N); warp tile 32x64 = 2 m16 x 8 n8.
// =====================================================================
template<bool KV>
__global__ void __launch_bounds__(256) k_qkv_mma(
    const float* __restrict__ A,
    const float* __restrict__ bias0, const float* __restrict__ bias1)
{
    __shared__ __align__(16) unsigned short As_hi[128][40], As_lo[128][40];
    __shared__ __align__(16) unsigned short Bs_hi[128][40], Bs_lo[128][40];

    const int t = threadIdx.x;
    const int lane = t & 31, wid = t >> 5;
    const int g = lane >> 2, tig = lane & 3;
    const int warpM = wid & 3, warpN = wid >> 2;
    const int row0 = blockIdx.x * 128;
    const int ysel = KV ? blockIdx.y : 0;

    const unsigned short* WT_hi = KV ? (g_WkvT_hi + (size_t)ysel * 128 * 512) : g_WqT_hi;
    const unsigned short* WT_lo = KV ? (g_WkvT_lo + (size_t)ysel * 128 * 512) : g_WqT_lo;
    const float* bias = KV ? (ysel ? bias1 : bias0) : bias0;
    unsigned* outp = KV ? (ysel ? g_Vm : g_Km) : g_Qm;

    float c[2][8][4];
#pragma unroll
    for (int mi = 0; mi < 2; mi++)
#pragma unroll
        for (int ni = 0; ni < 8; ni++)
#pragma unroll
            for (int q = 0; q < 4; q++) c[mi][ni][q] = 0.f;

    for (int kk = 0; kk < DD; kk += 32) {
        // prefetch globals
        float4 av[4];
#pragma unroll
        for (int i = 0; i < 4; i++) {
            int f = i * 256 + t, r = f >> 3, kq = (f & 7) * 4;
            av[i] = *(const float4*)(A + (size_t)(row0 + r) * DD + kk + kq);
        }
        uint4 bh4[2], bl4[2];
#pragma unroll
        for (int i = 0; i < 2; i++) {
            int f = i * 256 + t, n = f >> 2, kq = (f & 3) * 8;
            size_t idx = (size_t)n * 512 + kk + kq;
            bh4[i] = *(const uint4*)(WT_hi + idx);
            bl4[i] = *(const uint4*)(WT_lo + idx);
        }
        __syncthreads();
        // store A tile split
#pragma unroll
        for (int i = 0; i < 4; i++) {
            int f = i * 256 + t, r = f >> 3, kq = (f & 7) * 4;
            unsigned short h0,h1,h2,h3,l0,l1,l2,l3;
            split2(av[i].x, h0, l0); split2(av[i].y, h1, l1);
            split2(av[i].z, h2, l2); split2(av[i].w, h3, l3);
            *(uint2*)&As_hi[r][kq] = make_uint2((unsigned)h0 | ((unsigned)h1 << 16),
                                                (unsigned)h2 | ((unsigned)h3 << 16));
            *(uint2*)&As_lo[r][kq] = make_uint2((unsigned)l0 | ((unsigned)l1 << 16),
                                                (unsigned)l2 | ((unsigned)l3 << 16));
        }
#pragma unroll
        for (int i = 0; i < 2; i++) {
            int f = i * 256 + t, n = f >> 2, kq = (f & 3) * 8;
            *(uint4*)&Bs_hi[n][kq] = bh4[i];
            *(uint4*)&Bs_lo[n][kq] = bl4[i];
        }
        __syncthreads();
#pragma unroll
        for (int ks = 0; ks < 2; ks++) {
            const int kc = ks * 16 + tig * 2;
            unsigned ah[2][4], al[2][4];
#pragma unroll
            for (int mi = 0; mi < 2; mi++) {
                int rb = warpM * 32 + mi * 16;
                ah[mi][0] = *(const unsigned*)&As_hi[rb + g    ][kc];
                ah[mi][1] = *(const unsigned*)&As_hi[rb + g + 8][kc];
                ah[mi][2] = *(const unsigned*)&As_hi[rb + g    ][kc + 8];
                ah[mi][3] = *(const unsigned*)&As_hi[rb + g + 8][kc + 8];
                al[mi][0] = *(const unsigned*)&As_lo[rb + g    ][kc];
                al[mi][1] = *(const unsigned*)&As_lo[rb + g + 8][kc];
                al[mi][2] = *(const unsigned*)&As_lo[rb + g    ][kc + 8];
                al[mi][3] = *(const unsigned*)&As_lo[rb + g + 8][kc + 8];
            }
            unsigned bh[8][2], bl[8][2];
#pragma unroll
            for (int ni = 0; ni < 8; ni++) {
                int nb = warpN * 64 + ni * 8 + g;
                bh[ni][0] = *(const unsigned*)&Bs_hi[nb][kc];
                bh[ni][1] = *(const unsigned*)&Bs_hi[nb][kc + 8];
                bl[ni][0] = *(const unsigned*)&Bs_lo[nb][kc];
                bl[ni][1] = *(const unsigned*)&Bs_lo[nb][kc + 8];
            }
#pragma unroll
            for (int ni = 0; ni < 8; ni++)
#pragma unroll
                for (int mi = 0; mi < 2; mi++) {
                    mma16816(c[mi][ni], ah[mi], bh[ni]);
                    mma16816(c[mi][ni], ah[mi], bl[ni]);
                    mma16816(c[mi][ni], al[mi], bh[ni]);
                }
        }
    }
    // epilogue: bias + pack + store
#pragma unroll
    for (int mi = 0; mi < 2; mi++) {
        int r0 = row0 + warpM * 32 + mi * 16 + g;
#pragma unroll
        for (int ni = 0; ni < 8; ni++) {
            int col = warpN * 64 + ni * 8 + tig * 2;
            float b0f = bias[col], b1f = bias[col + 1];
            unsigned p00 = packf(c[mi][ni][0] + b0f);
            unsigned p01 = packf(c[mi][ni][1] + b1f);
            unsigned p10 = packf(c[mi][ni][2] + b0f);
            unsigned p11 = packf(c[mi][ni][3] + b1f);
            *(uint2*)&outp[(size_t)r0 * CC + col]       = make_uint2(p00, p01);
            *(uint2*)&outp[(size_t)(r0 + 8) * CC + col] = make_uint2(p10, p11);
        }
    }
}

// =====================================================================
// K2: partial scores (reads packed Qm/Km).
// =====================================================================
__global__ void __launch_bounds__(256) k_scores()
{
    __shared__ float Qs[128][32];
    __shared__ float Ks[128][32];
    const int t = threadIdx.x;
    const int chunk = blockIdx.x;
    const int bh = blockIdx.y;
    const int b = bh >> 2, h = bh & 3;
    const int rowbase = b * LL + chunk * 128;

#pragma unroll
    for (int i = 0; i < 4; i++) {
        int f = i * 256 + t;
        int r = f >> 3, j = (f & 7) * 4;
        uint4 q = *(const uint4*)(g_Qm + (size_t)(rowbase + r) * CC + h * DK + j);
        uint4 k = *(const uint4*)(g_Km + (size_t)(rowbase + r) * CC + h * DK + j);
        Qs[r][j+0] = unpackf(q.x); Qs[r][j+1] = unpackf(q.y);
        Qs[r][j+2] = unpackf(q.z); Qs[r][j+3] = unpackf(q.w);
        Ks[r][j+0] = unpackf(k.x); Ks[r][j+1] = unpackf(k.y);
        Ks[r][j+2] = unpackf(k.z); Ks[r][j+3] = unpackf(k.w);
    }
    __syncthreads();

    const int tile = t & 63, ly = t >> 6;
    const int d0 = (tile >> 3) * 4, e0 = (tile & 7) * 4;
    float acc[4][4];
#pragma unroll
    for (int r = 0; r < 4; r++)
#pragma unroll
        for (int c = 0; c < 4; c++) acc[r][c] = 0.f;

    for (int l = ly; l < 128; l += 4) {
        float4 q = *(const float4*)&Qs[l][d0];
        float4 k = *(const float4*)&Ks[l][e0];
        float qa[4] = {q.x,q.y,q.z,q.w};
        float ka[4] = {k.x,k.y,k.z,k.w};
#pragma unroll
        for (int r = 0; r < 4; r++)
#pragma unroll
            for (int c = 0; c < 4; c++)
                acc[r][c] = fmaf(qa[r], ka[c], acc[r][c]);
    }
    __syncthreads();
    float* red = &Qs[0][0];
#pragma unroll
    for (int r = 0; r < 4; r++)
#pragma unroll
        for (int c = 0; c < 4; c++) red[t*16 + r*4 + c] = acc[r][c];
    __syncthreads();
    if (t < 64) {
        const int dd0 = (t >> 3) * 4, ee0 = (t & 7) * 4;
#pragma unroll
        for (int i = 0; i < 16; i++) {
            float s = red[t*16+i] + red[(t+64)*16+i] + red[(t+128)*16+i] + red[(t+192)*16+i];
            int r = i >> 2, c = i & 3;
            g_part[(size_t)chunk * 65536 + bh*1024 + (dd0+r)*32 + (ee0+c)] = s;
        }
    }
}

// =====================================================================
// K3: reduce + softmax.
// =====================================================================
__global__ void __launch_bounds__(1024) k_softmax(float* __restrict__ attn_out)
{
    const int bh = blockIdx.x;
    const int t = threadIdx.x;
    float s = 0.f;
#pragma unroll
    for (int c = 0; c < NCHUNK; c++) s += g_part[(size_t)c*65536 + bh*1024 + t];
    s *= SCALE_F;
    float m = s;
#pragma unroll
    for (int o = 16; o; o >>= 1) m = fmaxf(m, __shfl_xor_sync(0xffffffffu, m, o));
    float ex = expf(s - m);
    float sum = ex;
#pragma unroll
    for (int o = 16; o; o >>= 1) sum += __shfl_xor_sync(0xffffffffu, sum, o);
    float a = ex / sum;
    g_attn[bh*1024 + t] = a;
    if (attn_out) attn_out[bh*1024 + t] = a;
}

// =====================================================================
// K4: WoEff transposed + bf16-split: g_WoT[b][m][e] = sum_d attn*Wo.
// =====================================================================
__global__ void __launch_bounds__(256) k_woeff(const float* __restrict__ Wo)
{
    __shared__ float at[4096];
    __shared__ float wo_s[128][32];
    const int m0 = blockIdx.x * 32;
    const int b  = blockIdx.y;
    const int t  = threadIdx.x;
#pragma unroll
    for (int i = 0; i < 4; i++) {
        int f = i*256 + t;
        *(float4*)&at[f*4] = *(const float4*)(g_attn + (size_t)b*4096 + f*4);
    }
#pragma unroll
    for (int i = 0; i < 4; i++) {
        int f = i*256 + t;
        int r = f >> 3, c = (f & 7) * 4;
        *(float4*)&wo_s[r][c] = *(const float4*)(Wo + (size_t)r*MM + m0 + c);
    }
    __syncthreads();
    const int tx = t & 31, ty = t >> 5;
#pragma unroll
    for (int i = 0; i < 16; i++) {
        int he = ty + 8*i;
        int h = he >> 5, e = he & 31;
        float s = 0.f;
#pragma unroll
        for (int d = 0; d < 32; d++)
            s = fmaf(at[h*1024 + d*32 + e], wo_s[h*32+d][tx], s);
        unsigned short hh, ll; split2(s, hh, ll);
        size_t o = ((size_t)b * 512 + (m0 + tx)) * 128 + he;
        g_WoT_hi[o] = hh; g_WoT_lo[o] = ll;
    }
}

// =====================================================================
// K5: final GEMM via bf16-split MMA.
// x = [Qm|Vm](packed) @ [WqoT ; WoT[b]]^T + (bqo+bo) -> g_X
// Same 128x128 tile / 8-warp layout as K1. K=256.
// =====================================================================
__global__ void __launch_bounds__(256) k_fgemm(
    const float* __restrict__ bqo, const float* __restrict__ bo)
{
    __shared__ __align__(16) unsigned short As_hi[128][40], As_lo[128][40];
    __shared__ __align__(16) unsigned short Bs_hi[128][40], Bs_lo[128][40];

    const int t = threadIdx.x;
    const int lane = t & 31, wid = t >> 5;
    const int g = lane >> 2, tig = lane & 3;
    const int warpM = wid & 3, warpN = wid >> 2;
    const int row0 = blockIdx.x * 128;
    const int nblk = blockIdx.y;           // 0..3
    const int b = row0 >> 12;

    float c[2][8][4];
#pragma unroll
    for (int mi = 0; mi < 2; mi++)
#pragma unroll
        for (int ni = 0; ni < 8; ni++)
#pragma unroll
            for (int q = 0; q < 4; q++) c[mi][ni][q] = 0.f;

    for (int kk = 0; kk < 256; kk += 32) {
        uint4 av[4];
#pragma unroll
        for (int i = 0; i < 4; i++) {
            int f = i * 256 + t, r = f >> 3, kq = (f & 7) * 4;
            int kg = kk + kq;
            const unsigned* src = (kg < 128)
                ? (g_Qm + (size_t)(row0 + r) * CC + kg)
                : (g_Vm + (size_t)(row0 + r) * CC + (kg - 128));
            av[i] = *(const uint4*)src;
        }
        uint4 bh4[2], bl4[2];
#pragma unroll
        for (int i = 0; i < 2; i++) {
            int f = i * 256 + t, n = f >> 2, kq = (f & 3) * 8;
            int ng = nblk * 128 + n;
            size_t idx;
            const unsigned short *sh, *sl;
            if (kk < 128) {
                idx = (size_t)ng * 128 + kk + kq;
                sh = g_WqoT_hi; sl = g_WqoT_lo;
            } else {
                idx = ((size_t)b * 512 + ng) * 128 + (kk - 128) + kq;
                sh = g_WoT_hi; sl = g_WoT_lo;
            }
            bh4[i] = *(const uint4*)(sh + idx);
            bl4[i] = *(const uint4*)(sl + idx);
        }
        __syncthreads();
#pragma unroll
        for (int i = 0; i < 4; i++) {
            int f = i * 256 + t, r = f >> 3, kq = (f & 7) * 4;
            // packed: low16 = hi, high16 = lo
            *(uint2*)&As_hi[r][kq] = make_uint2((av[i].x & 0xffffu) | ((av[i].y & 0xffffu) << 16),
                                                (av[i].z & 0xffffu) | ((av[i].w & 0xffffu) << 16));
            *(uint2*)&As_lo[r][kq] = make_uint2((av[i].x >> 16) | (av[i].y & 0xffff0000u),
                                                (av[i].z >> 16) | (av[i].w & 0xffff0000u));
        }
#pragma unroll
        for (int i = 0; i < 2; i++) {
            int f = i * 256 + t, n = f >> 2, kq = (f & 3) * 8;
            *(uint4*)&Bs_hi[n][kq] = bh4[i];
            *(uint4*)&Bs_lo[n][kq] = bl4[i];
        }
        __syncthreads();
#pragma unroll
        for (int ks = 0; ks < 2; ks++) {
            const int kc = ks * 16 + tig * 2;
            unsigned ah[2][4], al[2][4];
#pragma unroll
            for (int mi = 0; mi < 2; mi++) {
                int rb = warpM * 32 + mi * 16;
                ah[mi][0] = *(const unsigned*)&As_hi[rb + g    ][kc];
                ah[mi][1] = *(const unsigned*)&As_hi[rb + g + 8][kc];
                ah[mi][2] = *(const unsigned*)&As_hi[rb + g    ][kc + 8];
                ah[mi][3] = *(const unsigned*)&As_hi[rb + g + 8][kc + 8];
                al[mi][0] = *(const unsigned*)&As_lo[rb + g    ][kc];
                al[mi][1] = *(const unsigned*)&As_lo[rb + g + 8][kc];
                al[mi][2] = *(const unsigned*)&As_lo[rb + g    ][kc + 8];
                al[mi][3] = *(const unsigned*)&As_lo[rb + g + 8][kc + 8];
            }
            unsigned bh[8][2], bl[8][2];
#pragma unroll
            for (int ni = 0; ni < 8; ni++) {
                int nb = warpN * 64 + ni * 8 + g;
                bh[ni][0] = *(const unsigned*)&Bs_hi[nb][kc];
                bh[ni][1] = *(const unsigned*)&Bs_hi[nb][kc + 8];
                bl[ni][0] = *(const unsigned*)&Bs_lo[nb][kc];
                bl[ni][1] = *(const unsigned*)&Bs_lo[nb][kc + 8];
            }
#pragma unroll
            for (int ni = 0; ni < 8; ni++)
#pragma unroll
                for (int mi = 0; mi < 2; mi++) {
                    mma16816(c[mi][ni], ah[mi], bh[ni]);
                    mma16816(c[mi][ni], ah[mi], bl[ni]);
                    mma16816(c[mi][ni], al[mi], bh[ni]);
                }
        }
    }
    // epilogue: bias + fp32 store to g_X
#pragma unroll
    for (int mi = 0; mi < 2; mi++) {
        int r0 = row0 + warpM * 32 + mi * 16 + g;
#pragma unroll
        for (int ni = 0; ni < 8; ni++) {
            int col = nblk * 128 + warpN * 64 + ni * 8 + tig * 2;
            float b0f = bqo[col] + bo[col];
            float b1f = bqo[col + 1] + bo[col + 1];
            float2 v0 = make_float2(c[mi][ni][0] + b0f, c[mi][ni][1] + b1f);
            float2 v1 = make_float2(c[mi][ni][2] + b0f, c[mi][ni][3] + b1f);
            *(float2*)&g_X[(size_t)r0 * MM + col]       = v0;
            *(float2*)&g_X[(size_t)(r0 + 8) * MM + col] = v1;
        }
    }
}

// =====================================================================
// K6: LayerNorm over g_X rows -> Y. warp per row.
// =====================================================================
__global__ void __launch_bounds__(256) k_ln(
    const float* __restrict__ gamma, const float* __restrict__ beta,
    float* __restrict__ Y)
{
    const int t = threadIdx.x;
    const int lane = t & 31, wid = t >> 5;
    const int row = blockIdx.x * 8 + wid;

    float4 xv[4];
    float sum = 0.f, sq = 0.f;
#pragma unroll
    for (int j = 0; j < 4; j++) {
        int col = lane * 4 + j * 128;
        xv[j] = *(const float4*)(g_X + (size_t)row * MM + col);
        sum += xv[j].x + xv[j].y + xv[j].z + xv[j].w;
        sq = fmaf(xv[j].x, xv[j].x, sq);
        sq = fmaf(xv[j].y, xv[j].y, sq);
        sq = fmaf(xv[j].z, xv[j].z, sq);
        sq = fmaf(xv[j].w, xv[j].w, sq);
    }
#pragma unroll
    for (int o = 16; o; o >>= 1) {
        sum += __shfl_xor_sync(0xffffffffu, sum, o);
        sq  += __shfl_xor_sync(0xffffffffu, sq,  o);
    }
    float mu  = sum * (1.f/512.f);
    float var = sq * (1.f/512.f) - mu*mu;
    float inv = rsqrtf(var + 1e-5f);
#pragma unroll
    for (int j = 0; j < 4; j++) {
        int col = lane * 4 + j * 128;
        float4 g4 = *(const float4*)(gamma + col);
        float4 e4 = *(const float4*)(beta + col);
        float4 o4;
        o4.x = (xv[j].x - mu) * inv * g4.x + e4.x;
        o4.y = (xv[j].y - mu) * inv * g4.y + e4.y;
        o4.z = (xv[j].z - mu) * inv * g4.z + e4.z;
        o4.w = (xv[j].w - mu) * inv * g4.w + e4.w;
        *(float4*)(Y + (size_t)row * MM + col) = o4;
    }
}

// =====================================================================
extern "C" void kernel_launch(void* const* d_in, const int* in_sizes, int n_in,
                              void* d_out, int out_size)
{
    const float* Q_in  = (const float*)d_in[0];
    const float* KV_in = (const float*)d_in[1];
    const float* Wq    = (const float*)d_in[2];
    const float* bq    = (const float*)d_in[3];
    const float* Wk    = (const float*)d_in[4];
    const float* bk    = (const float*)d_in[5];
    const float* Wv    = (const float*)d_in[6];
    const float* bv    = (const float*)d_in[7];
    const float* Wo    = (const float*)d_in[8];
    const float* bo    = (const float*)d_in[9];
    const float* Wqo   = (const float*)d_in[10];
    const float* bqo   = (const float*)d_in[11];
    const float* gamma = (const float*)d_in[12];
    const float* beta  = (const float*)d_in[13];
    float* out = (float*)d_out;

    const long long y_elems = (long long)NR * MM;
    const long long a_elems = (long long)BB * HH * DK * DK;
    float* attn_out = ((long long)out_size >= y_elems + a_elems) ? (out + y_elems) : nullptr;

    k_prep<<<1024, 256>>>(Wq, Wk, Wv, Wqo);
    k_qkv_mma<false><<<dim3(NR/128, 1), 256>>>(Q_in,  bq, bq);
    k_qkv_mma<true ><<<dim3(NR/128, 2), 256>>>(KV_in, bk, bv);
    k_scores<<<dim3(NCHUNK, BB*HH), 256>>>();
    k_softmax<<<BB*HH, 1024>>>(attn_out);
    k_woeff<<<dim3(MM/32, BB), 256>>>(Wo);
    k_fgemm<<<dim3(NR/128, MM/128), 256>>>(bqo, bo);
    k_ln<<<NR/8, 256>>>(gamma, beta, out);
}

// round 6
// speedup vs baseline: 3.2254x; 1.0087x over previous
#include <cuda_runtime.h>
#include <cuda_bf16.h>
#include <math.h>

// ---------------- problem constants ----------------
#define BB   16
#define LL   4096
#define NR   (BB*LL)      // 65536 rows
#define DD   512
#define CC   128
#define HH   4
#define DK   32
#define MM   512
#define NCHUNK 32
#define SCALE_F 0.17677669529663687f

// ---------------- device scratch ----------------
// Qm/Km/Vm stored packed: low16 = bf16(hi), high16 = bf16(residual)
__device__ unsigned g_Qm[(size_t)NR * CC];
__device__ unsigned g_Km[(size_t)NR * CC];
__device__ unsigned g_Vm[(size_t)NR * CC];
__device__ float    g_part[(size_t)NCHUNK * BB * HH * DK * DK];
__device__ float    g_attn[BB * HH * DK * DK];
// transposed + split weights: [n][k] layout, k contiguous
__device__ unsigned short g_WqT_hi [128 * 512], g_WqT_lo [128 * 512];
__device__ unsigned short g_WkvT_hi[256 * 512], g_WkvT_lo[256 * 512];
__device__ unsigned short g_WqoT_hi[512 * 128], g_WqoT_lo[512 * 128];
__device__ unsigned short g_WoT_hi [16 * 512 * 128], g_WoT_lo[16 * 512 * 128];

// ---------------- helpers ----------------
__device__ __forceinline__ void split2(float x, unsigned short& h, unsigned short& l)
{
    __nv_bfloat16 hb = __float2bfloat16(x);
    float r = x - __bfloat162float(hb);
    __nv_bfloat16 lb = __float2bfloat16(r);
    h = __bfloat16_as_ushort(hb);
    l = __bfloat16_as_ushort(lb);
}
__device__ __forceinline__ unsigned packf(float x)
{
    unsigned short h, l; split2(x, h, l);
    return (unsigned)h | ((unsigned)l << 16);
}
__device__ __forceinline__ float unpackf(unsigned u)
{
    float h = __bfloat162float(__ushort_as_bfloat16((unsigned short)(u & 0xffffu)));
    float l = __bfloat162float(__ushort_as_bfloat16((unsigned short)(u >> 16)));
    return h + l;
}
__device__ __forceinline__ void mma16816(float* c, const unsigned* a, const unsigned* b)
{
    asm volatile(
        "mma.sync.aligned.m16n8k16.row.col.f32.bf16.bf16.f32 "
        "{%0,%1,%2,%3}, {%4,%5,%6,%7}, {%8,%9}, {%0,%1,%2,%3};"
        : "+f"(c[0]), "+f"(c[1]), "+f"(c[2]), "+f"(c[3])
        : "r"(a[0]), "r"(a[1]), "r"(a[2]), "r"(a[3]), "r"(b[0]), "r"(b[1]));
}

// =====================================================================
// k_prep: build transposed, bf16-split weight copies.
// =====================================================================
__global__ void __launch_bounds__(256) k_prep(
    const float* __restrict__ Wq, const float* __restrict__ Wk,
    const float* __restrict__ Wv, const float* __restrict__ Wqo)
{
    int e = blockIdx.x * 256 + threadIdx.x;      // 0..262143
    unsigned short h, l;
    if (e < 65536) {                              // WqT [128][512]
        int n = e >> 9, k = e & 511;
        split2(Wq[(size_t)k * 128 + n], h, l);
        g_WqT_hi[(size_t)n * 512 + k] = h; g_WqT_lo[(size_t)n * 512 + k] = l;
    } else if (e < 196608) {                      // WkvT [256][512]
        int e2 = e - 65536;
        int n = e2 >> 9, k = e2 & 511;
        float v = (n < 128) ? Wk[(size_t)k * 128 + n] : Wv[(size_t)k * 128 + (n - 128)];
        split2(v, h, l);
        g_WkvT_hi[(size_t)n * 512 + k] = h; g_WkvT_lo[(size_t)n * 512 + k] = l;
    } else {                                      // WqoT [512][128]
        int e2 = e - 196608;
        int n = e2 >> 7, k = e2 & 127;
        split2(Wqo[(size_t)k * 512 + n], h, l);
        g_WqoT_hi[(size_t)n * 128 + k] = h; g_WqoT_lo[(size_t)n * 128 + k] = l;
    }
}

// =====================================================================
// K1: unified QKV projection via bf16-split MMA. grid (NR/128, 3):
// y=0 -> Qm from Q_in@Wq, y=1 -> Km from KV_in@Wk, y=2 -> Vm from KV_in@Wv.
// C(128x128 per CTA). 8 warps 4(M) x 2(N); warp tile 32x64 = 2 m16 x 8 n8.
// =====================================================================
__global__ void __launch_bounds__(256) k_qkv_mma(
    const float* __restrict__ Q_in, const float* __restrict__ KV_in,
    const float* __restrict__ bq, const float* __restrict__ bk,
    const float* __restrict__ bv)
{
    __shared__ __align__(16) unsigned short As_hi[128][40], As_lo[128][40];
    __shared__ __align__(16) unsigned short Bs_hi[128][40], Bs_lo[128][40];

    const int t = threadIdx.x;
    const int lane = t & 31, wid = t >> 5;
    const int g = lane >> 2, tig = lane & 3;
    const int warpM = wid & 3, warpN = wid >> 2;
    const int row0 = blockIdx.x * 128;
    const int y = blockIdx.y;

    const float* A = (y == 0) ? Q_in : KV_in;
    const unsigned short* WT_hi = (y == 0) ? g_WqT_hi : (g_WkvT_hi + (size_t)(y - 1) * 128 * 512);
    const unsigned short* WT_lo = (y == 0) ? g_WqT_lo : (g_WkvT_lo + (size_t)(y - 1) * 128 * 512);
    const float* bias = (y == 0) ? bq : ((y == 1) ? bk : bv);
    unsigned* outp = (y == 0) ? g_Qm : ((y == 1) ? g_Km : g_Vm);

    float c[2][8][4];
#pragma unroll
    for (int mi = 0; mi < 2; mi++)
#pragma unroll
        for (int ni = 0; ni < 8; ni++)
#pragma unroll
            for (int q = 0; q < 4; q++) c[mi][ni][q] = 0.f;

    for (int kk = 0; kk < DD; kk += 32) {
        float4 av[4];
#pragma unroll
        for (int i = 0; i < 4; i++) {
            int f = i * 256 + t, r = f >> 3, kq = (f & 7) * 4;
            av[i] = *(const float4*)(A + (size_t)(row0 + r) * DD + kk + kq);
        }
        uint4 bh4[2], bl4[2];
#pragma unroll
        for (int i = 0; i < 2; i++) {
            int f = i * 256 + t, n = f >> 2, kq = (f & 3) * 8;
            size_t idx = (size_t)n * 512 + kk + kq;
            bh4[i] = *(const uint4*)(WT_hi + idx);
            bl4[i] = *(const uint4*)(WT_lo + idx);
        }
        __syncthreads();
#pragma unroll
        for (int i = 0; i < 4; i++) {
            int f = i * 256 + t, r = f >> 3, kq = (f & 7) * 4;
            unsigned short h0,h1,h2,h3,l0,l1,l2,l3;
            split2(av[i].x, h0, l0); split2(av[i].y, h1, l1);
            split2(av[i].z, h2, l2); split2(av[i].w, h3, l3);
            *(uint2*)&As_hi[r][kq] = make_uint2((unsigned)h0 | ((unsigned)h1 << 16),
                                                (unsigned)h2 | ((unsigned)h3 << 16));
            *(uint2*)&As_lo[r][kq] = make_uint2((unsigned)l0 | ((unsigned)l1 << 16),
                                                (unsigned)l2 | ((unsigned)l3 << 16));
        }
#pragma unroll
        for (int i = 0; i < 2; i++) {
            int f = i * 256 + t, n = f >> 2, kq = (f & 3) * 8;
            *(uint4*)&Bs_hi[n][kq] = bh4[i];
            *(uint4*)&Bs_lo[n][kq] = bl4[i];
        }
        __syncthreads();
#pragma unroll
        for (int ks = 0; ks < 2; ks++) {
            const int kc = ks * 16 + tig * 2;
            unsigned ah[2][4], al[2][4];
#pragma unroll
            for (int mi = 0; mi < 2; mi++) {
                int rb = warpM * 32 + mi * 16;
                ah[mi][0] = *(const unsigned*)&As_hi[rb + g    ][kc];
                ah[mi][1] = *(const unsigned*)&As_hi[rb + g + 8][kc];
                ah[mi][2] = *(const unsigned*)&As_hi[rb + g    ][kc + 8];
                ah[mi][3] = *(const unsigned*)&As_hi[rb + g + 8][kc + 8];
                al[mi][0] = *(const unsigned*)&As_lo[rb + g    ][kc];
                al[mi][1] = *(const unsigned*)&As_lo[rb + g + 8][kc];
                al[mi][2] = *(const unsigned*)&As_lo[rb + g    ][kc + 8];
                al[mi][3] = *(const unsigned*)&As_lo[rb + g + 8][kc + 8];
            }
#pragma unroll
            for (int ni = 0; ni < 8; ni++) {
                int nb = warpN * 64 + ni * 8 + g;
                unsigned bh[2], bl[2];
                bh[0] = *(const unsigned*)&Bs_hi[nb][kc];
                bh[1] = *(const unsigned*)&Bs_hi[nb][kc + 8];
                bl[0] = *(const unsigned*)&Bs_lo[nb][kc];
                bl[1] = *(const unsigned*)&Bs_lo[nb][kc + 8];
#pragma unroll
                for (int mi = 0; mi < 2; mi++) {
                    mma16816(c[mi][ni], ah[mi], bh);
                    mma16816(c[mi][ni], ah[mi], bl);
                    mma16816(c[mi][ni], al[mi], bh);
                }
            }
        }
    }
#pragma unroll
    for (int mi = 0; mi < 2; mi++) {
        int r0 = row0 + warpM * 32 + mi * 16 + g;
#pragma unroll
        for (int ni = 0; ni < 8; ni++) {
            int col = warpN * 64 + ni * 8 + tig * 2;
            float b0f = bias[col], b1f = bias[col + 1];
            unsigned p00 = packf(c[mi][ni][0] + b0f);
            unsigned p01 = packf(c[mi][ni][1] + b1f);
            unsigned p10 = packf(c[mi][ni][2] + b0f);
            unsigned p11 = packf(c[mi][ni][3] + b1f);
            *(uint2*)&outp[(size_t)r0 * CC + col]       = make_uint2(p00, p01);
            *(uint2*)&outp[(size_t)(r0 + 8) * CC + col] = make_uint2(p10, p11);
        }
    }
}

// =====================================================================
// K2: partial scores (reads packed Qm/Km).
// =====================================================================
__global__ void __launch_bounds__(256) k_scores()
{
    __shared__ float Qs[128][32];
    __shared__ float Ks[128][32];
    const int t = threadIdx.x;
    const int chunk = blockIdx.x;
    const int bh = blockIdx.y;
    const int b = bh >> 2, h = bh & 3;
    const int rowbase = b * LL + chunk * 128;

#pragma unroll
    for (int i = 0; i < 4; i++) {
        int f = i * 256 + t;
        int r = f >> 3, j = (f & 7) * 4;
        uint4 q = *(const uint4*)(g_Qm + (size_t)(rowbase + r) * CC + h * DK + j);
        uint4 k = *(const uint4*)(g_Km + (size_t)(rowbase + r) * CC + h * DK + j);
        Qs[r][j+0] = unpackf(q.x); Qs[r][j+1] = unpackf(q.y);
        Qs[r][j+2] = unpackf(q.z); Qs[r][j+3] = unpackf(q.w);
        Ks[r][j+0] = unpackf(k.x); Ks[r][j+1] = unpackf(k.y);
        Ks[r][j+2] = unpackf(k.z); Ks[r][j+3] = unpackf(k.w);
    }
    __syncthreads();

    const int tile = t & 63, ly = t >> 6;
    const int d0 = (tile >> 3) * 4, e0 = (tile & 7) * 4;
    float acc[4][4];
#pragma unroll
    for (int r = 0; r < 4; r++)
#pragma unroll
        for (int c = 0; c < 4; c++) acc[r][c] = 0.f;

    for (int l = ly; l < 128; l += 4) {
        float4 q = *(const float4*)&Qs[l][d0];
        float4 k = *(const float4*)&Ks[l][e0];
        float qa[4] = {q.x,q.y,q.z,q.w};
        float ka[4] = {k.x,k.y,k.z,k.w};
#pragma unroll
        for (int r = 0; r < 4; r++)
#pragma unroll
            for (int c = 0; c < 4; c++)
                acc[r][c] = fmaf(qa[r], ka[c], acc[r][c]);
    }
    __syncthreads();
    float* red = &Qs[0][0];
#pragma unroll
    for (int r = 0; r < 4; r++)
#pragma unroll
        for (int c = 0; c < 4; c++) red[t*16 + r*4 + c] = acc[r][c];
    __syncthreads();
    if (t < 64) {
        const int dd0 = (t >> 3) * 4, ee0 = (t & 7) * 4;
#pragma unroll
        for (int i = 0; i < 16; i++) {
            float s = red[t*16+i] + red[(t+64)*16+i] + red[(t+128)*16+i] + red[(t+192)*16+i];
            int r = i >> 2, c = i & 3;
            g_part[(size_t)chunk * 65536 + bh*1024 + (dd0+r)*32 + (ee0+c)] = s;
        }
    }
}

// =====================================================================
// K3: reduce + softmax.
// =====================================================================
__global__ void __launch_bounds__(1024) k_softmax(float* __restrict__ attn_out)
{
    const int bh = blockIdx.x;
    const int t = threadIdx.x;
    float s = 0.f;
#pragma unroll
    for (int c = 0; c < NCHUNK; c++) s += g_part[(size_t)c*65536 + bh*1024 + t];
    s *= SCALE_F;
    float m = s;
#pragma unroll
    for (int o = 16; o; o >>= 1) m = fmaxf(m, __shfl_xor_sync(0xffffffffu, m, o));
    float ex = expf(s - m);
    float sum = ex;
#pragma unroll
    for (int o = 16; o; o >>= 1) sum += __shfl_xor_sync(0xffffffffu, sum, o);
    float a = ex / sum;
    g_attn[bh*1024 + t] = a;
    if (attn_out) attn_out[bh*1024 + t] = a;
}

// =====================================================================
// K4: WoEff transposed + bf16-split: g_WoT[b][m][e] = sum_d attn*Wo.
// =====================================================================
__global__ void __launch_bounds__(256) k_woeff(const float* __restrict__ Wo)
{
    __shared__ float at[4096];
    __shared__ float wo_s[128][32];
    const int m0 = blockIdx.x * 32;
    const int b  = blockIdx.y;
    const int t  = threadIdx.x;
#pragma unroll
    for (int i = 0; i < 4; i++) {
        int f = i*256 + t;
        *(float4*)&at[f*4] = *(const float4*)(g_attn + (size_t)b*4096 + f*4);
    }
#pragma unroll
    for (int i = 0; i < 4; i++) {
        int f = i*256 + t;
        int r = f >> 3, c = (f & 7) * 4;
        *(float4*)&wo_s[r][c] = *(const float4*)(Wo + (size_t)r*MM + m0 + c);
    }
    __syncthreads();
    const int tx = t & 31, ty = t >> 5;
#pragma unroll
    for (int i = 0; i < 16; i++) {
        int he = ty + 8*i;
        int h = he >> 5, e = he & 31;
        float s = 0.f;
#pragma unroll
        for (int d = 0; d < 32; d++)
            s = fmaf(at[h*1024 + d*32 + e], wo_s[h*32+d][tx], s);
        unsigned short hh, ll; split2(s, hh, ll);
        size_t o = ((size_t)b * 512 + (m0 + tx)) * 128 + he;
        g_WoT_hi[o] = hh; g_WoT_lo[o] = ll;
    }
}

// =====================================================================
// K5: fused final GEMM + LayerNorm.
// x = [Qm|Vm](packed) @ [WqoT ; WoT[b]]^T + (bqo+bo); y = LN(x)*gamma+beta.
// Tile: 64 rows x FULL 512 cols, BK=16. 256 threads = 8 warps (2M x 4N);
// warp tile 32x128 = 2 m16 x 16 n8. LN via quad-shuffle + smem cross-warp.
// =====================================================================
__global__ void __launch_bounds__(256) k_fgemm_ln(
    const float* __restrict__ bqo, const float* __restrict__ bo,
    const float* __restrict__ gamma, const float* __restrict__ beta,
    float* __restrict__ Y)
{
    __shared__ __align__(16) unsigned short As_hi[64][20],  As_lo[64][20];
    __shared__ __align__(16) unsigned short Bs_hi[512][20], Bs_lo[512][20];
    __shared__ float redS[4][64], redQ[4][64];

    const int t = threadIdx.x;
    const int lane = t & 31, wid = t >> 5;
    const int g = lane >> 2, tig = lane & 3;
    const int warpM = wid & 1, warpN = wid >> 1;   // 2M x 4N
    const int row0 = blockIdx.x * 64;
    const int b = row0 >> 12;
    const int kc = tig * 2;

    float c[2][16][4];
#pragma unroll
    for (int mi = 0; mi < 2; mi++)
#pragma unroll
        for (int ni = 0; ni < 16; ni++)
#pragma unroll
            for (int q = 0; q < 4; q++) c[mi][ni][q] = 0.f;

    for (int kk = 0; kk < 256; kk += 16) {
        // A: 64 rows x 16 k (packed hi|lo), 256 uint4 total -> 1 per thread
        uint4 av;
        {
            int r = t >> 2, kq = (t & 3) * 4;
            int kg = kk + kq;
            const unsigned* src = (kg < 128)
                ? (g_Qm + (size_t)(row0 + r) * CC + kg)
                : (g_Vm + (size_t)(row0 + r) * CC + (kg - 128));
            av = *(const uint4*)src;
        }
        // B: 512 n x 16 k, per half 1024 uint4 -> 4 per thread
        uint4 bh4[4], bl4[4];
#pragma unroll
        for (int i = 0; i < 4; i++) {
            int f = i * 256 + t;
            int n = f >> 1, kq = (f & 1) * 8;
            size_t idx;
            const unsigned short *sh, *sl;
            if (kk < 128) {
                idx = (size_t)n * 128 + kk + kq;
                sh = g_WqoT_hi; sl = g_WqoT_lo;
            } else {
                idx = ((size_t)b * 512 + n) * 128 + (kk - 128) + kq;
                sh = g_WoT_hi; sl = g_WoT_lo;
            }
            bh4[i] = *(const uint4*)(sh + idx);
            bl4[i] = *(const uint4*)(sl + idx);
        }
        __syncthreads();
        {
            int r = t >> 2, kq = (t & 3) * 4;
            *(uint2*)&As_hi[r][kq] = make_uint2((av.x & 0xffffu) | ((av.y & 0xffffu) << 16),
                                                (av.z & 0xffffu) | ((av.w & 0xffffu) << 16));
            *(uint2*)&As_lo[r][kq] = make_uint2((av.x >> 16) | (av.y & 0xffff0000u),
                                                (av.z >> 16) | (av.w & 0xffff0000u));
        }
#pragma unroll
        for (int i = 0; i < 4; i++) {
            int f = i * 256 + t;
            int n = f >> 1, kq = (f & 1) * 8;
            *(uint2*)&Bs_hi[n][kq]     = make_uint2(bh4[i].x, bh4[i].y);
            *(uint2*)&Bs_hi[n][kq + 4] = make_uint2(bh4[i].z, bh4[i].w);
            *(uint2*)&Bs_lo[n][kq]     = make_uint2(bl4[i].x, bl4[i].y);
            *(uint2*)&Bs_lo[n][kq + 4] = make_uint2(bl4[i].z, bl4[i].w);
        }
        __syncthreads();

        unsigned ah[2][4], al[2][4];
#pragma unroll
        for (int mi = 0; mi < 2; mi++) {
            int rb = warpM * 32 + mi * 16;
            ah[mi][0] = *(const unsigned*)&As_hi[rb + g    ][kc];
            ah[mi][1] = *(const unsigned*)&As_hi[rb + g + 8][kc];
            ah[mi][2] = *(const unsigned*)&As_hi[rb + g    ][kc + 8];
            ah[mi][3] = *(const unsigned*)&As_hi[rb + g + 8][kc + 8];
            al[mi][0] = *(const unsigned*)&As_lo[rb + g    ][kc];
            al[mi][1] = *(const unsigned*)&As_lo[rb + g + 8][kc];
            al[mi][2] = *(const unsigned*)&As_lo[rb + g    ][kc + 8];
            al[mi][3] = *(const unsigned*)&As_lo[rb + g + 8][kc + 8];
        }
#pragma unroll
        for (int ni = 0; ni < 16; ni++) {
            int nb = warpN * 128 + ni * 8 + g;
            unsigned bh[2], bl[2];
            bh[0] = *(const unsigned*)&Bs_hi[nb][kc];
            bh[1] = *(const unsigned*)&Bs_hi[nb][kc + 8];
            bl[0] = *(const unsigned*)&Bs_lo[nb][kc];
            bl[1] = *(const unsigned*)&Bs_lo[nb][kc + 8];
#pragma unroll
            for (int mi = 0; mi < 2; mi++) {
                mma16816(c[mi][ni], ah[mi], bh);
                mma16816(c[mi][ni], ah[mi], bl);
                mma16816(c[mi][ni], al[mi], bh);
            }
        }
    }

    // ---- epilogue: bias, LN stats, normalize, store ----
#pragma unroll
    for (int mi = 0; mi < 2; mi++) {
        float sA = 0.f, qA = 0.f, sB = 0.f, qB = 0.f;
#pragma unroll
        for (int ni = 0; ni < 16; ni++) {
            int col = warpN * 128 + ni * 8 + kc;
            float b0 = bqo[col] + bo[col];
            float b1 = bqo[col + 1] + bo[col + 1];
            float x0 = c[mi][ni][0] + b0, x1 = c[mi][ni][1] + b1;
            float x2 = c[mi][ni][2] + b0, x3 = c[mi][ni][3] + b1;
            c[mi][ni][0] = x0; c[mi][ni][1] = x1;
            c[mi][ni][2] = x2; c[mi][ni][3] = x3;
            sA += x0 + x1; qA = fmaf(x0, x0, fmaf(x1, x1, qA));
            sB += x2 + x3; qB = fmaf(x2, x2, fmaf(x3, x3, qB));
        }
#pragma unroll
        for (int o = 1; o <= 2; o <<= 1) {
            sA += __shfl_xor_sync(0xffffffffu, sA, o);
            qA += __shfl_xor_sync(0xffffffffu, qA, o);
            sB += __shfl_xor_sync(0xffffffffu, sB, o);
            qB += __shfl_xor_sync(0xffffffffu, qB, o);
        }
        if (tig == 0) {
            int rl = warpM * 32 + mi * 16 + g;
            redS[warpN][rl] = sA;     redQ[warpN][rl] = qA;
            redS[warpN][rl + 8] = sB; redQ[warpN][rl + 8] = qB;
        }
    }
    __syncthreads();
#pragma unroll
    for (int mi = 0; mi < 2; mi++) {
        int rlA = warpM * 32 + mi * 16 + g;
        int rlB = rlA + 8;
        float sumA = redS[0][rlA] + redS[1][rlA] + redS[2][rlA] + redS[3][rlA];
        float sqA  = redQ[0][rlA] + redQ[1][rlA] + redQ[2][rlA] + redQ[3][rlA];
        float sumB = redS[0][rlB] + redS[1][rlB] + redS[2][rlB] + redS[3][rlB];
        float sqB  = redQ[0][rlB] + redQ[1][rlB] + redQ[2][rlB] + redQ[3][rlB];
        float muA = sumA * (1.f/512.f);
        float invA = rsqrtf(sqA * (1.f/512.f) - muA*muA + 1e-5f);
        float muB = sumB * (1.f/512.f);
        float invB = rsqrtf(sqB * (1.f/512.f) - muB*muB + 1e-5f);
#pragma unroll
        for (int ni = 0; ni < 16; ni++) {
            int col = warpN * 128 + ni * 8 + kc;
            float g0 = gamma[col], g1 = gamma[col + 1];
            float e0 = beta[col],  e1 = beta[col + 1];
            float2 vA = make_float2((c[mi][ni][0] - muA) * invA * g0 + e0,
                                    (c[mi][ni][1] - muA) * invA * g1 + e1);
            float2 vB = make_float2((c[mi][ni][2] - muB) * invB * g0 + e0,
                                    (c[mi][ni][3] - muB) * invB * g1 + e1);
            *(float2*)&Y[(size_t)(row0 + rlA) * MM + col] = vA;
            *(float2*)&Y[(size_t)(row0 + rlB) * MM + col] = vB;
        }
    }
}

// =====================================================================
extern "C" void kernel_launch(void* const* d_in, const int* in_sizes, int n_in,
                              void* d_out, int out_size)
{
    const float* Q_in  = (const float*)d_in[0];
    const float* KV_in = (const float*)d_in[1];
    const float* Wq    = (const float*)d_in[2];
    const float* bq    = (const float*)d_in[3];
    const float* Wk    = (const float*)d_in[4];
    const float* bk    = (const float*)d_in[5];
    const float* Wv    = (const float*)d_in[6];
    const float* bv    = (const float*)d_in[7];
    const float* Wo    = (const float*)d_in[8];
    const float* bo    = (const float*)d_in[9];
    const float* Wqo   = (const float*)d_in[10];
    const float* bqo   = (const float*)d_in[11];
    const float* gamma = (const float*)d_in[12];
    const float* beta  = (const float*)d_in[13];
    float* out = (float*)d_out;

    const long long y_elems = (long long)NR * MM;
    const long long a_elems = (long long)BB * HH * DK * DK;
    float* attn_out = ((long long)out_size >= y_elems + a_elems) ? (out + y_elems) : nullptr;

    k_prep<<<1024, 256>>>(Wq, Wk, Wv, Wqo);
    k_qkv_mma<<<dim3(NR/128, 3), 256>>>(Q_in, KV_in, bq, bk, bv);
    k_scores<<<dim3(NCHUNK, BB*HH), 256>>>();
    k_softmax<<<BB*HH, 1024>>>(attn_out);
    k_woeff<<<dim3(MM/32, BB), 256>>>(Wo);
    k_fgemm_ln<<<NR/64, 256>>>(bqo, bo, gamma, beta, out);
}

// round 10
// speedup vs baseline: 4.5417x; 1.4081x over previous
#include <cuda_runtime.h>
#include <cuda_bf16.h>
#include <cstdint>
#include <math.h>

// ---------------- problem constants ----------------
#define BB   16
#define LL   4096
#define NR   (BB*LL)      // 65536 rows
#define DD   512
#define CC   128
#define HH   4
#define DK   32
#define MM   512
#define NCHUNK 32
#define SCALE_F 0.17677669529663687f

// ---------------- device scratch ----------------
__device__ unsigned g_Qm[(size_t)NR * CC];
__device__ unsigned g_Km[(size_t)NR * CC];
__device__ unsigned g_Vm[(size_t)NR * CC];
__device__ float    g_part[(size_t)NCHUNK * BB * HH * DK * DK];
__device__ float    g_attn[BB * HH * DK * DK];
// transposed + split weights: [n][k] layout, k contiguous
__device__ unsigned short g_WqT_hi [128 * 512], g_WqT_lo [128 * 512];
__device__ unsigned short g_WkvT_hi[256 * 512], g_WkvT_lo[256 * 512];
__device__ unsigned short g_WqoT_hi[512 * 128], g_WqoT_lo[512 * 128];
__device__ unsigned short g_WoT_hi [16 * 512 * 128], g_WoT_lo[16 * 512 * 128];

// ---------------- helpers ----------------
__device__ __forceinline__ void split2(float x, unsigned short& h, unsigned short& l)
{
    __nv_bfloat16 hb = __float2bfloat16(x);
    float r = x - __bfloat162float(hb);
    __nv_bfloat16 lb = __float2bfloat16(r);
    h = __bfloat16_as_ushort(hb);
    l = __bfloat16_as_ushort(lb);
}
__device__ __forceinline__ unsigned packf(float x)
{
    unsigned short h, l; split2(x, h, l);
    return (unsigned)h | ((unsigned)l << 16);
}
__device__ __forceinline__ float unpackf(unsigned u)
{
    float h = __bfloat162float(__ushort_as_bfloat16((unsigned short)(u & 0xffffu)));
    float l = __bfloat162float(__ushort_as_bfloat16((unsigned short)(u >> 16)));
    return h + l;
}
__device__ __forceinline__ void mma16816(float* c, const unsigned* a, const unsigned* b)
{
    asm volatile(
        "mma.sync.aligned.m16n8k16.row.col.f32.bf16.bf16.f32 "
        "{%0,%1,%2,%3}, {%4,%5,%6,%7}, {%8,%9}, {%0,%1,%2,%3};"
        : "+f"(c[0]), "+f"(c[1]), "+f"(c[2]), "+f"(c[3])
        : "r"(a[0]), "r"(a[1]), "r"(a[2]), "r"(a[3]), "r"(b[0]), "r"(b[1]));
}
__device__ __forceinline__ uint32_t smem_u32(const void* p)
{
    uint32_t a;
    asm("{ .reg .u64 t; cvta.to.shared.u64 t, %1; cvt.u32.u64 %0, t; }" : "=r"(a) : "l"(p));
    return a;
}
__device__ __forceinline__ void ldsm4(uint32_t* r, uint32_t a)
{
    asm volatile("ldmatrix.sync.aligned.m8n8.x4.shared.b16 {%0,%1,%2,%3}, [%4];"
        : "=r"(r[0]), "=r"(r[1]), "=r"(r[2]), "=r"(r[3]) : "r"(a));
}

// =====================================================================
// k_prep: build transposed, bf16-split weight copies.
// =====================================================================
__global__ void __launch_bounds__(256) k_prep(
    const float* __restrict__ Wq, const float* __restrict__ Wk,
    const float* __restrict__ Wv, const float* __restrict__ Wqo)
{
    int e = blockIdx.x * 256 + threadIdx.x;      // 0..262143
    unsigned short h, l;
    if (e < 65536) {                              // WqT [128][512]
        int n = e >> 9, k = e & 511;
        split2(Wq[(size_t)k * 128 + n], h, l);
        g_WqT_hi[(size_t)n * 512 + k] = h; g_WqT_lo[(size_t)n * 512 + k] = l;
    } else if (e < 196608) {                      // WkvT [256][512]
        int e2 = e - 65536;
        int n = e2 >> 9, k = e2 & 511;
        float v = (n < 128) ? Wk[(size_t)k * 128 + n] : Wv[(size_t)k * 128 + (n - 128)];
        split2(v, h, l);
        g_WkvT_hi[(size_t)n * 512 + k] = h; g_WkvT_lo[(size_t)n * 512 + k] = l;
    } else {                                      // WqoT [512][128]
        int e2 = e - 196608;
        int n = e2 >> 7, k = e2 & 127;
        split2(Wqo[(size_t)k * 512 + n], h, l);
        g_WqoT_hi[(size_t)n * 128 + k] = h; g_WqoT_lo[(size_t)n * 128 + k] = l;
    }
}

// =====================================================================
// K1: QKV projection, HMMA + ldmatrix + double-buffered smem.
// grid (NR/128, 3): y=0 Qm, y=1 Km, y=2 Vm. 8 warps 4Mx2N, warp 32x64.
// BK=32. Row stride 80B (40 halves). Dyn smem: 2 bufs x 40KB.
// =====================================================================
__global__ void __launch_bounds__(256) k_qkv_mma(
    const float* __restrict__ Q_in, const float* __restrict__ KV_in,
    const float* __restrict__ bq, const float* __restrict__ bk,
    const float* __restrict__ bv)
{
    extern __shared__ __align__(16) char smem[];
    const int t = threadIdx.x;
    const int lane = t & 31, wid = t >> 5;
    const int g = lane >> 2, tig = lane & 3;
    const int warpM = wid & 3, warpN = wid >> 2;
    const int row0 = blockIdx.x * 128;
    const int y = blockIdx.y;
    const uint32_t sb = smem_u32(smem);

    const float* A = (y == 0) ? Q_in : KV_in;
    const unsigned short* WT_hi = (y == 0) ? g_WqT_hi : (g_WkvT_hi + (size_t)(y - 1) * 128 * 512);
    const unsigned short* WT_lo = (y == 0) ? g_WqT_lo : (g_WkvT_lo + (size_t)(y - 1) * 128 * 512);
    const float* bias = (y == 0) ? bq : ((y == 1) ? bk : bv);
    unsigned* outp = (y == 0) ? g_Qm : ((y == 1) ? g_Km : g_Vm);

    // layout per buffer: As_hi @0, As_lo @10240, Bs_hi @20480, Bs_lo @30720
    const uint32_t BUF = 40960;
    const uint32_t aoff = (uint32_t)((warpM * 32 + (lane & 7) + ((lane >> 3) & 1) * 8) * 80
                                     + ((lane >> 4) & 1) * 16);
    const uint32_t boff = (uint32_t)((warpN * 64 + (lane & 7) + ((lane >> 4) & 1) * 8) * 80
                                     + ((lane >> 3) & 1) * 16);

    float c[2][8][4];
#pragma unroll
    for (int mi = 0; mi < 2; mi++)
#pragma unroll
        for (int ni = 0; ni < 8; ni++)
#pragma unroll
            for (int q = 0; q < 4; q++) c[mi][ni][q] = 0.f;

    float4 av[4];
    uint4 bh4[2], bl4[2];

    auto gload = [&](int cc) {
        const int kk = cc * 32;
#pragma unroll
        for (int i = 0; i < 4; i++) {
            int f = i * 256 + t, r = f >> 3, kq = (f & 7) * 4;
            av[i] = *(const float4*)(A + (size_t)(row0 + r) * DD + kk + kq);
        }
#pragma unroll
        for (int i = 0; i < 2; i++) {
            int f = i * 256 + t, n = f >> 2, k8 = (f & 3) * 8;
            size_t idx = (size_t)n * DD + kk + k8;
            bh4[i] = *(const uint4*)(WT_hi + idx);
            bl4[i] = *(const uint4*)(WT_lo + idx);
        }
    };
    auto sstore = [&](int buf) {
        char* b0 = smem + buf * BUF;
#pragma unroll
        for (int i = 0; i < 4; i++) {
            int f = i * 256 + t, r = f >> 3, kq = (f & 7) * 4;
            unsigned short h0,h1,h2,h3,l0,l1,l2,l3;
            split2(av[i].x, h0, l0); split2(av[i].y, h1, l1);
            split2(av[i].z, h2, l2); split2(av[i].w, h3, l3);
            int off = r * 80 + kq * 2;
            *(uint2*)(b0 + off) = make_uint2((unsigned)h0 | ((unsigned)h1 << 16),
                                             (unsigned)h2 | ((unsigned)h3 << 16));
            *(uint2*)(b0 + 10240 + off) = make_uint2((unsigned)l0 | ((unsigned)l1 << 16),
                                                     (unsigned)l2 | ((unsigned)l3 << 16));
        }
#pragma unroll
        for (int i = 0; i < 2; i++) {
            int f = i * 256 + t, n = f >> 2, k8 = (f & 3) * 8;
            int off = n * 80 + k8 * 2;
            *(uint4*)(b0 + 20480 + off) = bh4[i];
            *(uint4*)(b0 + 30720 + off) = bl4[i];
        }
    };
    auto compute = [&](int buf) {
        const uint32_t base = sb + buf * BUF;
#pragma unroll
        for (int ks = 0; ks < 2; ks++) {
            const uint32_t ko = ks * 32;
            uint32_t ah[2][4], al[2][4];
            ldsm4(ah[0], base + aoff + ko);
            ldsm4(ah[1], base + aoff + 1280 + ko);
            ldsm4(al[0], base + 10240 + aoff + ko);
            ldsm4(al[1], base + 10240 + aoff + 1280 + ko);
#pragma unroll
            for (int p = 0; p < 4; p++) {
                uint32_t bh[4], bl[4];
                ldsm4(bh, base + 20480 + boff + p * 1280 + ko);
                ldsm4(bl, base + 30720 + boff + p * 1280 + ko);
#pragma unroll
                for (int q = 0; q < 2; q++)
#pragma unroll
                    for (int mi = 0; mi < 2; mi++) {
                        mma16816(c[mi][2*p+q], ah[mi], bh + 2*q);
                        mma16816(c[mi][2*p+q], ah[mi], bl + 2*q);
                        mma16816(c[mi][2*p+q], al[mi], bh + 2*q);
                    }
            }
        }
    };

    gload(0);
    sstore(0);
    __syncthreads();
#pragma unroll 1
    for (int cc = 0; cc < 16; cc++) {
        const int buf = cc & 1;
        if (cc < 15) gload(cc + 1);
        compute(buf);
        if (cc < 15) {
            sstore(buf ^ 1);
            __syncthreads();
        }
    }

    // epilogue: bias + pack + store
#pragma unroll
    for (int mi = 0; mi < 2; mi++) {
        int r0 = row0 + warpM * 32 + mi * 16 + g;
#pragma unroll
        for (int ni = 0; ni < 8; ni++) {
            int col = warpN * 64 + ni * 8 + tig * 2;
            float b0f = bias[col], b1f = bias[col + 1];
            unsigned p00 = packf(c[mi][ni][0] + b0f);
            unsigned p01 = packf(c[mi][ni][1] + b1f);
            unsigned p10 = packf(c[mi][ni][2] + b0f);
            unsigned p11 = packf(c[mi][ni][3] + b1f);
            *(uint2*)&outp[(size_t)r0 * CC + col]       = make_uint2(p00, p01);
            *(uint2*)&outp[(size_t)(r0 + 8) * CC + col] = make_uint2(p10, p11);
        }
    }
}

// =====================================================================
// K2: partial scores (reads packed Qm/Km).
// =====================================================================
__global__ void __launch_bounds__(256) k_scores()
{
    __shared__ float Qs[128][32];
    __shared__ float Ks[128][32];
    const int t = threadIdx.x;
    const int chunk = blockIdx.x;
    const int bh = blockIdx.y;
    const int b = bh >> 2, h = bh & 3;
    const int rowbase = b * LL + chunk * 128;

#pragma unroll
    for (int i = 0; i < 4; i++) {
        int f = i * 256 + t;
        int r = f >> 3, j = (f & 7) * 4;
        uint4 q = *(const uint4*)(g_Qm + (size_t)(rowbase + r) * CC + h * DK + j);
        uint4 k = *(const uint4*)(g_Km + (size_t)(rowbase + r) * CC + h * DK + j);
        Qs[r][j+0] = unpackf(q.x); Qs[r][j+1] = unpackf(q.y);
        Qs[r][j+2] = unpackf(q.z); Qs[r][j+3] = unpackf(q.w);
        Ks[r][j+0] = unpackf(k.x); Ks[r][j+1] = unpackf(k.y);
        Ks[r][j+2] = unpackf(k.z); Ks[r][j+3] = unpackf(k.w);
    }
    __syncthreads();

    const int tile = t & 63, ly = t >> 6;
    const int d0 = (tile >> 3) * 4, e0 = (tile & 7) * 4;
    float acc[4][4];
#pragma unroll
    for (int r = 0; r < 4; r++)
#pragma unroll
        for (int c = 0; c < 4; c++) acc[r][c] = 0.f;

    for (int l = ly; l < 128; l += 4) {
        float4 q = *(const float4*)&Qs[l][d0];
        float4 k = *(const float4*)&Ks[l][e0];
        float qa[4] = {q.x,q.y,q.z,q.w};
        float ka[4] = {k.x,k.y,k.z,k.w};
#pragma unroll
        for (int r = 0; r < 4; r++)
#pragma unroll
            for (int c = 0; c < 4; c++)
                acc[r][c] = fmaf(qa[r], ka[c], acc[r][c]);
    }
    __syncthreads();
    float* red = &Qs[0][0];
#pragma unroll
    for (int r = 0; r < 4; r++)
#pragma unroll
        for (int c = 0; c < 4; c++) red[t*16 + r*4 + c] = acc[r][c];
    __syncthreads();
    if (t < 64) {
        const int dd0 = (t >> 3) * 4, ee0 = (t & 7) * 4;
#pragma unroll
        for (int i = 0; i < 16; i++) {
            float s = red[t*16+i] + red[(t+64)*16+i] + red[(t+128)*16+i] + red[(t+192)*16+i];
            int r = i >> 2, c = i & 3;
            g_part[(size_t)chunk * 65536 + bh*1024 + (dd0+r)*32 + (ee0+c)] = s;
        }
    }
}

// =====================================================================
// K3: reduce + softmax.
// =====================================================================
__global__ void __launch_bounds__(1024) k_softmax(float* __restrict__ attn_out)
{
    const int bh = blockIdx.x;
    const int t = threadIdx.x;
    float s = 0.f;
#pragma unroll
    for (int c = 0; c < NCHUNK; c++) s += g_part[(size_t)c*65536 + bh*1024 + t];
    s *= SCALE_F;
    float m = s;
#pragma unroll
    for (int o = 16; o; o >>= 1) m = fmaxf(m, __shfl_xor_sync(0xffffffffu, m, o));
    float ex = expf(s - m);
    float sum = ex;
#pragma unroll
    for (int o = 16; o; o >>= 1) sum += __shfl_xor_sync(0xffffffffu, sum, o);
    float a = ex / sum;
    g_attn[bh*1024 + t] = a;
    if (attn_out) attn_out[bh*1024 + t] = a;
}

// =====================================================================
// K4: WoEff transposed + bf16-split: g_WoT[b][m][e] = sum_d attn*Wo.
// =====================================================================
__global__ void __launch_bounds__(256) k_woeff(const float* __restrict__ Wo)
{
    __shared__ float at[4096];
    __shared__ float wo_s[128][32];
    const int m0 = blockIdx.x * 32;
    const int b  = blockIdx.y;
    const int t  = threadIdx.x;
#pragma unroll
    for (int i = 0; i < 4; i++) {
        int f = i*256 + t;
        *(float4*)&at[f*4] = *(const float4*)(g_attn + (size_t)b*4096 + f*4);
    }
#pragma unroll
    for (int i = 0; i < 4; i++) {
        int f = i*256 + t;
        int r = f >> 3, c = (f & 7) * 4;
        *(float4*)&wo_s[r][c] = *(const float4*)(Wo + (size_t)r*MM + m0 + c);
    }
    __syncthreads();
    const int tx = t & 31, ty = t >> 5;
#pragma unroll
    for (int i = 0; i < 16; i++) {
        int he = ty + 8*i;
        int h = he >> 5, e = he & 31;
        float s = 0.f;
#pragma unroll
        for (int d = 0; d < 32; d++)
            s = fmaf(at[h*1024 + d*32 + e], wo_s[h*32+d][tx], s);
        unsigned short hh, ll; split2(s, hh, ll);
        size_t o = ((size_t)b * 512 + (m0 + tx)) * 128 + he;
        g_WoT_hi[o] = hh; g_WoT_lo[o] = ll;
    }
}

// =====================================================================
// K5: fused final GEMM + LN, HMMA + ldmatrix + double buffer.
// BM=64, BN=512 (full M), BK=16. 8 warps 2Mx4N, warp 32x128.
// Row stride 48B (24 halves). Dyn smem 2 x 54KB.
// =====================================================================
__global__ void __launch_bounds__(256) k_fgemm_ln(
    const float* __restrict__ bqo, const float* __restrict__ bo,
    const float* __restrict__ gamma, const float* __restrict__ beta,
    float* __restrict__ Y)
{
    extern __shared__ __align__(16) char smem[];
    __shared__ float redS[4][64], redQ[4][64];

    const int t = threadIdx.x;
    const int lane = t & 31, wid = t >> 5;
    const int g = lane >> 2, tig = lane & 3;
    const int warpM = wid & 1, warpN = wid >> 1;   // 2M x 4N
    const int row0 = blockIdx.x * 64;
    const int b = row0 >> 12;
    const int kc = tig * 2;
    const uint32_t sb = smem_u32(smem);

    // per buffer: As_hi @0 (3072), As_lo @3072, Bs_hi @6144 (24576), Bs_lo @30720
    const uint32_t BUF = 55296;
    const uint32_t aoff = (uint32_t)((warpM * 32 + (lane & 7) + ((lane >> 3) & 1) * 8) * 48
                                     + ((lane >> 4) & 1) * 16);
    const uint32_t boff = (uint32_t)((warpN * 128 + (lane & 7) + ((lane >> 4) & 1) * 8) * 48
                                     + ((lane >> 3) & 1) * 16);

    float c[2][16][4];
#pragma unroll
    for (int mi = 0; mi < 2; mi++)
#pragma unroll
        for (int ni = 0; ni < 16; ni++)
#pragma unroll
            for (int q = 0; q < 4; q++) c[mi][ni][q] = 0.f;

    uint4 av;
    uint4 bh4[4], bl4[4];

    auto gload = [&](int cc) {
        const int kk = cc * 16;
        {
            int r = t >> 2, kq = (t & 3) * 4;
            int kg = kk + kq;
            const unsigned* src = (kk < 128)
                ? (g_Qm + (size_t)(row0 + r) * CC + kg)
                : (g_Vm + (size_t)(row0 + r) * CC + (kg - 128));
            av = *(const uint4*)src;
        }
#pragma unroll
        for (int i = 0; i < 4; i++) {
            int f = i * 256 + t;
            int n = f >> 1, k8 = (f & 1) * 8;
            size_t idx;
            const unsigned short *sh, *sl;
            if (kk < 128) {
                idx = (size_t)n * 128 + kk + k8;
                sh = g_WqoT_hi; sl = g_WqoT_lo;
            } else {
                idx = ((size_t)b * 512 + n) * 128 + (kk - 128) + k8;
                sh = g_WoT_hi; sl = g_WoT_lo;
            }
            bh4[i] = *(const uint4*)(sh + idx);
            bl4[i] = *(const uint4*)(sl + idx);
        }
    };
    auto sstore = [&](int buf) {
        char* b0 = smem + buf * BUF;
        {
            int r = t >> 2, kq = (t & 3) * 4;
            int off = r * 48 + kq * 2;
            *(uint2*)(b0 + off) = make_uint2((av.x & 0xffffu) | ((av.y & 0xffffu) << 16),
                                             (av.z & 0xffffu) | ((av.w & 0xffffu) << 16));
            *(uint2*)(b0 + 3072 + off) = make_uint2((av.x >> 16) | (av.y & 0xffff0000u),
                                                    (av.z >> 16) | (av.w & 0xffff0000u));
        }
#pragma unroll
        for (int i = 0; i < 4; i++) {
            int f = i * 256 + t;
            int n = f >> 1, k8 = (f & 1) * 8;
            int off = n * 48 + k8 * 2;
            *(uint4*)(b0 + 6144 + off) = bh4[i];
            *(uint4*)(b0 + 30720 + off) = bl4[i];
        }
    };
    auto compute = [&](int buf) {
        const uint32_t base = sb + buf * BUF;
        uint32_t ah[2][4], al[2][4];
        ldsm4(ah[0], base + aoff);
        ldsm4(ah[1], base + aoff + 768);
        ldsm4(al[0], base + 3072 + aoff);
        ldsm4(al[1], base + 3072 + aoff + 768);
#pragma unroll
        for (int p = 0; p < 8; p++) {
            uint32_t bh[4], bl[4];
            ldsm4(bh, base + 6144 + boff + p * 768);
            ldsm4(bl, base + 30720 + boff + p * 768);
#pragma unroll
            for (int q = 0; q < 2; q++)
#pragma unroll
                for (int mi = 0; mi < 2; mi++) {
                    mma16816(c[mi][2*p+q], ah[mi], bh + 2*q);
                    mma16816(c[mi][2*p+q], ah[mi], bl + 2*q);
                    mma16816(c[mi][2*p+q], al[mi], bh + 2*q);
                }
        }
    };

    gload(0);
    sstore(0);
    __syncthreads();
#pragma unroll 1
    for (int cc = 0; cc < 16; cc++) {
        const int buf = cc & 1;
        if (cc < 15) gload(cc + 1);
        compute(buf);
        if (cc < 15) {
            sstore(buf ^ 1);
            __syncthreads();
        }
    }

    // ---- epilogue: bias, LN stats, normalize, store ----
#pragma unroll
    for (int mi = 0; mi < 2; mi++) {
        float sA = 0.f, qA = 0.f, sB = 0.f, qB = 0.f;
#pragma unroll
        for (int ni = 0; ni < 16; ni++) {
            int col = warpN * 128 + ni * 8 + kc;
            float b0 = bqo[col] + bo[col];
            float b1 = bqo[col + 1] + bo[col + 1];
            float x0 = c[mi][ni][0] + b0, x1 = c[mi][ni][1] + b1;
            float x2 = c[mi][ni][2] + b0, x3 = c[mi][ni][3] + b1;
            c[mi][ni][0] = x0; c[mi][ni][1] = x1;
            c[mi][ni][2] = x2; c[mi][ni][3] = x3;
            sA += x0 + x1; qA = fmaf(x0, x0, fmaf(x1, x1, qA));
            sB += x2 + x3; qB = fmaf(x2, x2, fmaf(x3, x3, qB));
        }
#pragma unroll
        for (int o = 1; o <= 2; o <<= 1) {
            sA += __shfl_xor_sync(0xffffffffu, sA, o);
            qA += __shfl_xor_sync(0xffffffffu, qA, o);
            sB += __shfl_xor_sync(0xffffffffu, sB, o);
            qB += __shfl_xor_sync(0xffffffffu, qB, o);
        }
        if (tig == 0) {
            int rl = warpM * 32 + mi * 16 + g;
            redS[warpN][rl] = sA;     redQ[warpN][rl] = qA;
            redS[warpN][rl + 8] = sB; redQ[warpN][rl + 8] = qB;
        }
    }
    __syncthreads();
#pragma unroll
    for (int mi = 0; mi < 2; mi++) {
        int rlA = warpM * 32 + mi * 16 + g;
        int rlB = rlA + 8;
        float sumA = redS[0][rlA] + redS[1][rlA] + redS[2][rlA] + redS[3][rlA];
        float sqA  = redQ[0][rlA] + redQ[1][rlA] + redQ[2][rlA] + redQ[3][rlA];
        float sumB = redS[0][rlB] + redS[1][rlB] + redS[2][rlB] + redS[3][rlB];
        float sqB  = redQ[0][rlB] + redQ[1][rlB] + redQ[2][rlB] + redQ[3][rlB];
        float muA = sumA * (1.f/512.f);
        float invA = rsqrtf(sqA * (1.f/512.f) - muA*muA + 1e-5f);
        float muB = sumB * (1.f/512.f);
        float invB = rsqrtf(sqB * (1.f/512.f) - muB*muB + 1e-5f);
#pragma unroll
        for (int ni = 0; ni < 16; ni++) {
            int col = warpN * 128 + ni * 8 + kc;
            float g0 = gamma[col], g1 = gamma[col + 1];
            float e0 = beta[col],  e1 = beta[col + 1];
            float2 vA = make_float2((c[mi][ni][0] - muA) * invA * g0 + e0,
                                    (c[mi][ni][1] - muA) * invA * g1 + e1);
            float2 vB = make_float2((c[mi][ni][2] - muB) * invB * g0 + e0,
                                    (c[mi][ni][3] - muB) * invB * g1 + e1);
            *(float2*)&Y[(size_t)(row0 + rlA) * MM + col] = vA;
            *(float2*)&Y[(size_t)(row0 + rlB) * MM + col] = vB;
        }
    }
}

// =====================================================================
extern "C" void kernel_launch(void* const* d_in, const int* in_sizes, int n_in,
                              void* d_out, int out_size)
{
    const float* Q_in  = (const float*)d_in[0];
    const float* KV_in = (const float*)d_in[1];
    const float* Wq    = (const float*)d_in[2];
    const float* bq    = (const float*)d_in[3];
    const float* Wk    = (const float*)d_in[4];
    const float* bk    = (const float*)d_in[5];
    const float* Wv    = (const float*)d_in[6];
    const float* bv    = (const float*)d_in[7];
    const float* Wo    = (const float*)d_in[8];
    const float* bo    = (const float*)d_in[9];
    const float* Wqo   = (const float*)d_in[10];
    const float* bqo   = (const float*)d_in[11];
    const float* gamma = (const float*)d_in[12];
    const float* beta  = (const float*)d_in[13];
    float* out = (float*)d_out;

    const long long y_elems = (long long)NR * MM;
    const long long a_elems = (long long)BB * HH * DK * DK;
    float* attn_out = ((long long)out_size >= y_elems + a_elems) ? (out + y_elems) : nullptr;

    const int SMQ = 2 * 40960;   // 80 KB
    const int SMF = 2 * 55296;   // 108 KB
    cudaFuncSetAttribute(k_qkv_mma,  cudaFuncAttributeMaxDynamicSharedMemorySize, SMQ);
    cudaFuncSetAttribute(k_fgemm_ln, cudaFuncAttributeMaxDynamicSharedMemorySize, SMF);

    k_prep<<<1024, 256>>>(Wq, Wk, Wv, Wqo);
    k_qkv_mma<<<dim3(NR/128, 3), 256, SMQ>>>(Q_in, KV_in, bq, bk, bv);
    k_scores<<<dim3(NCHUNK, BB*HH), 256>>>();
    k_softmax<<<BB*HH, 1024>>>(attn_out);
    k_woeff<<<dim3(MM/32, BB), 256>>>(Wo);
    k_fgemm_ln<<<NR/64, 256, SMF>>>(bqo, bo, gamma, beta, out);
}